// round 12
// baseline (speedup 1.0000x reference)
#include <cuda_runtime.h>

typedef unsigned long long u64;

// ---------------------------------------------------------------------------
// Packed fp32x2 helpers (sm_100-family: 2x fp32 throughput packed pipe)
// ---------------------------------------------------------------------------
union F2 {
    u64    u;
    float2 f;
};

static __device__ __forceinline__ u64 ffma2(u64 a, u64 b, u64 c) {
    u64 d;
    asm("fma.rn.f32x2 %0, %1, %2, %3;" : "=l"(d) : "l"(a), "l"(b), "l"(c));
    return d;
}
static __device__ __forceinline__ float sigf(float z) {
    return __fdividef(1.0f, 1.0f + __expf(-z));
}

// ---------------------------------------------------------------------------
// Compile-time scalar constants
// ---------------------------------------------------------------------------
constexpr int NW2 = 738;   // natural float2 weight pairs {W[k][2a], W[k][2a+1]}
constexpr int NB2 = 55;    // natural float2 bias pairs (+1 scalar slot)

constexpr int THREADS = 128;
constexpr int ROWS_PER_BLOCK = 4 * THREADS;   // 4 independent rows per thread

struct Params {
    const float* W[10];
    const float* b[10];
};

// ---------------------------------------------------------------------------
// Column-packed partial layer: output pairs a in [J2B, J2B+J2N).
// Weight operand = NATURAL float2 pair from smem (one LDS.64 feeds 4 FFMA2).
// Disjoint column ranges across passes -> every weight loaded exactly once.
// Splitting caps accumulator liveness so 3 CTAs/SM fit.
// ---------------------------------------------------------------------------
template <int IN, int OUT, int J2B, int J2N, bool RELU>
static __device__ __forceinline__ void layer_part(
    const float2* __restrict__ sw, const float2* __restrict__ sb,
    F2 in[4][10], F2 out[4][10])
{
    constexpr int H = OUT / 2;   // column-pair stride in weight array

    // Bias init for this column range
#pragma unroll
    for (int a = J2B; a < J2B + J2N; ++a) {
        const u64 bb = *reinterpret_cast<const u64*>(sb + a);
#pragma unroll
        for (int r = 0; r < 4; ++r) out[r][a].u = bb;
    }

#pragma unroll
    for (int k = 0; k < IN; ++k) {
        // Broadcast x_k per row: {x,x} built in registers (alu pipe, cheap)
        F2 xd[4];
#pragma unroll
        for (int r = 0; r < 4; ++r) {
            const float v = (k & 1) ? in[r][k >> 1].f.y : in[r][k >> 1].f.x;
            xd[r].f.x = v;
            xd[r].f.y = v;
        }
#pragma unroll
        for (int a = J2B; a < J2B + J2N; ++a) {
            const u64 w = *reinterpret_cast<const u64*>(sw + k * H + a); // LDS.64
#pragma unroll
            for (int r = 0; r < 4; ++r)
                out[r][a].u = ffma2(xd[r].u, w, out[r][a].u);
        }
    }

    if (RELU) {
#pragma unroll
        for (int a = J2B; a < J2B + J2N; ++a)
#pragma unroll
            for (int r = 0; r < 4; ++r) {
                out[r][a].f.x = fmaxf(out[r][a].f.x, 0.0f);
                out[r][a].f.y = fmaxf(out[r][a].f.y, 0.0f);
            }
    }
}

// Full layer: optionally j-blocked into two disjoint column halves.
template <int IN, int OUT, bool RELU, bool SPLIT>
static __device__ __forceinline__ void layer(
    const float2* __restrict__ sw, const float2* __restrict__ sb,
    F2 in[4][10], F2 out[4][10])
{
    static_assert(IN % 2 == 0 && OUT % 2 == 0, "even dims");
    constexpr int H = OUT / 2;
    if constexpr (SPLIT) {
        constexpr int H0 = (H + 1) / 2;
        layer_part<IN, OUT, 0,  H0,     RELU>(sw, sb, in, out);
        layer_part<IN, OUT, H0, H - H0, RELU>(sw, sb, in, out);
    } else {
        layer_part<IN, OUT, 0, H, RELU>(sw, sb, in, out);
    }
}

__global__ void __launch_bounds__(THREADS, 3)
mlp_fused_kernel(const float* __restrict__ x, float* __restrict__ out,
                 Params p, int rows)
{
    // Function-local constexpr arrays (legal in device code, fully folded).
    constexpr int DIMS[11]  = {8, 20, 18, 16, 14, 12, 10, 8, 6, 4, 1};
    constexpr int WOFF2[10] = {0, 80, 260, 404, 516, 600, 660, 700, 724, 736};
    constexpr int BOFF2[9]  = {0, 10, 19, 27, 34, 40, 45, 49, 52};   // pairs; last-bias at 54

    __shared__ float2 sW[NW2];   // natural {W[k][2a], W[k][2a+1]} pairs
    __shared__ float2 sB[NB2];   // natural {b_2a, b_2a+1} pairs; sB[54] = {b9, 0}

    const int tid = threadIdx.x;

    // --- Stage weights + biases (straight contiguous float2 copies) -------
#pragma unroll
    for (int l = 0; l < 9; ++l) {
        const int n2 = DIMS[l] * DIMS[l + 1] / 2;
        const float2* __restrict__ Wsrc = (const float2*)p.W[l];
        for (int i = tid; i < n2; i += THREADS)
            sW[WOFF2[l] + i] = Wsrc[i];
        if (tid < DIMS[l + 1] / 2)
            sB[BOFF2[l] + tid] = ((const float2*)p.b[l])[tid];
    }
    if (tid < 2)   // last layer W (4 floats = 2 natural pairs)
        sW[736 + tid] = ((const float2*)p.W[9])[tid];
    if (tid == 0)  // last layer bias as {b, 0}
        sB[54] = make_float2(p.b[9][0], 0.0f);
    __syncthreads();

    // --- Row assignment: 4 independent rows per thread, coalesced ---------
    const long base = (long)blockIdx.x * ROWS_PER_BLOCK;
    const int r0 = (int)base + tid;
    const int r1 = r0 + THREADS;
    const int r2 = r0 + 2 * THREADS;
    const int r3 = r0 + 3 * THREADS;
    const bool g0 = r0 < rows, g1 = r1 < rows, g2 = r2 < rows, g3 = r3 < rows;

    const float4* __restrict__ X = (const float4*)x;
    const float4 z4 = make_float4(0.f, 0.f, 0.f, 0.f);
    float4 va[4], vb[4];
    va[0] = g0 ? X[2 * r0] : z4;  vb[0] = g0 ? X[2 * r0 + 1] : z4;
    va[1] = g1 ? X[2 * r1] : z4;  vb[1] = g1 ? X[2 * r1 + 1] : z4;
    va[2] = g2 ? X[2 * r2] : z4;  vb[2] = g2 ? X[2 * r2 + 1] : z4;
    va[3] = g3 ? X[2 * r3] : z4;  vb[3] = g3 ? X[2 * r3 + 1] : z4;

    // Ping-pong banks: [row][pair], pair a = {z_2a, z_2a+1} (natural packing)
    F2 A[4][10], B[4][10];
#pragma unroll
    for (int r = 0; r < 4; ++r) {
        A[r][0].f = make_float2(va[r].x, va[r].y);
        A[r][1].f = make_float2(va[r].z, va[r].w);
        A[r][2].f = make_float2(vb[r].x, vb[r].y);
        A[r][3].f = make_float2(vb[r].z, vb[r].w);
    }

    // --- 9 even layers (ping-pong A <-> B) --------------------------------
    // Only the two liveness-peak layers are split (caps regs for 3 CTAs/SM).
    layer< 8, 20, true, false>(sW + WOFF2[0], sB + BOFF2[0], A, B);
    layer<20, 18, true, true >(sW + WOFF2[1], sB + BOFF2[1], B, A);
    layer<18, 16, true, true >(sW + WOFF2[2], sB + BOFF2[2], A, B);
    layer<16, 14, true, false>(sW + WOFF2[3], sB + BOFF2[3], B, A);
    layer<14, 12, true, false>(sW + WOFF2[4], sB + BOFF2[4], A, B);
    layer<12, 10, true, false>(sW + WOFF2[5], sB + BOFF2[5], B, A);
    layer<10,  8, true, false>(sW + WOFF2[6], sB + BOFF2[6], A, B);
    layer< 8,  6, true, false>(sW + WOFF2[7], sB + BOFF2[7], B, A);
    layer< 6,  4, true, false>(sW + WOFF2[8], sB + BOFF2[8], A, B);

    // --- Last layer (4 -> 1): natural pairs line up perfectly -------------
    const u64 w01 = *reinterpret_cast<const u64*>(sW + 736);
    const u64 w23 = *reinterpret_cast<const u64*>(sW + 737);
    const u64 bz  = *reinterpret_cast<const u64*>(sB + 54);   // {b, 0}
    float z[4];
#pragma unroll
    for (int r = 0; r < 4; ++r) {
        F2 t;
        t.u = ffma2(B[r][0].u, w01, bz);
        t.u = ffma2(B[r][1].u, w23, t.u);
        z[r] = t.f.x + t.f.y;
    }

    // --- Sigmoid + store --------------------------------------------------
    if (g0) out[r0] = sigf(z[0]);
    if (g1) out[r1] = sigf(z[1]);
    if (g2) out[r2] = sigf(z[2]);
    if (g3) out[r3] = sigf(z[3]);
}

extern "C" void kernel_launch(void* const* d_in, const int* in_sizes, int n_in,
                              void* d_out, int out_size)
{
    const float* x = (const float*)d_in[0];
    Params p;
    for (int i = 0; i < 10; ++i) {
        p.W[i] = (const float*)d_in[1 + 2 * i];
        p.b[i] = (const float*)d_in[2 + 2 * i];
    }
    const int rows = in_sizes[0] / 8;   // x is [rows, 8] fp32
    const int grid = (rows + ROWS_PER_BLOCK - 1) / ROWS_PER_BLOCK;
    mlp_fused_kernel<<<grid, THREADS>>>(x, (float*)d_out, p, rows);
}

// round 13
// speedup vs baseline: 1.0980x; 1.0980x over previous
#include <cuda_runtime.h>

typedef unsigned long long u64;

// ---------------------------------------------------------------------------
// Packed fp32x2 helpers (sm_100-family: 2x fp32 throughput packed pipe)
// ---------------------------------------------------------------------------
union F2 {
    u64    u;
    float2 f;
};

static __device__ __forceinline__ u64 ffma2(u64 a, u64 b, u64 c) {
    u64 d;
    asm("fma.rn.f32x2 %0, %1, %2, %3;" : "=l"(d) : "l"(a), "l"(b), "l"(c));
    return d;
}
static __device__ __forceinline__ float sigf(float z) {
    return __fdividef(1.0f, 1.0f + __expf(-z));
}

// ---------------------------------------------------------------------------
// Constant-bank weight storage: weights are warp-uniform -> serve them from
// the CONSTANT PORT (LDC/LDCU), which is a separate HW path from the smem
// crossbar / L1tex pipe that every prior variant was bound to.
// Layout: [0,1476) raw row-major W0..W9 ; [1476,1585) b0..b9.
// ---------------------------------------------------------------------------
constexpr int NWF   = 1476;
constexpr int NALL  = 1476 + 109;   // + biases
__constant__ __align__(16) float cAll[NALL + 3];
__device__   __align__(16) float g_stage[NALL + 3];

constexpr int THREADS = 128;
constexpr int ROWS_PER_BLOCK = 4 * THREADS;   // 4 independent rows per thread

struct Params {
    const float* W[10];
    const float* b[10];
};

// ---------------------------------------------------------------------------
// Gather kernel: pack all W/b (device buffers) into g_stage (device global).
// Runs once per replay; ~1.6K floats, negligible.
// ---------------------------------------------------------------------------
__global__ void gather_kernel(Params p)
{
    constexpr int DIMS[11] = {8, 20, 18, 16, 14, 12, 10, 8, 6, 4, 1};
    constexpr int WOFF[10] = {0, 160, 520, 808, 1032, 1200, 1320, 1400, 1448, 1472};
    constexpr int BOFF[10] = {0, 20, 38, 54, 68, 80, 90, 98, 104, 108};
    const int tid = threadIdx.x;
#pragma unroll
    for (int l = 0; l < 10; ++l) {
        const int n = DIMS[l] * DIMS[l + 1];
        for (int i = tid; i < n; i += THREADS)
            g_stage[WOFF[l] + i] = p.W[l][i];
        for (int i = tid; i < DIMS[l + 1]; i += THREADS)
            g_stage[NWF + BOFF[l] + i] = p.b[l][i];
    }
}

// ---------------------------------------------------------------------------
// Column-packed layer, weights from the constant bank with COMPILE-TIME
// offsets (LDC.64 with immediate addressing; uniform-promotable to ULDC).
// Accumulators hold natural output pairs {z_2a, z_2a+1}; activation
// broadcast {x_k,x_k} built in registers. One LDC.64 feeds 4 FFMA2.
// ---------------------------------------------------------------------------
template <int IN, int OUT, int WO, int BO, bool RELU>
static __device__ __forceinline__ void layer(F2 in[4][10], F2 out[4][10])
{
    static_assert(IN % 2 == 0 && OUT % 2 == 0, "even dims");
    constexpr int H = OUT / 2;

    // Bias init: natural pairs from constant bank
#pragma unroll
    for (int a = 0; a < H; ++a) {
        const u64 bb = *reinterpret_cast<const u64*>(cAll + NWF + BO + 2 * a);
#pragma unroll
        for (int r = 0; r < 4; ++r) out[r][a].u = bb;
    }

#pragma unroll
    for (int k = 0; k < IN; ++k) {
        // Broadcast x_k per row: {x,x} in registers
        F2 xd[4];
#pragma unroll
        for (int r = 0; r < 4; ++r) {
            const float v = (k & 1) ? in[r][k >> 1].f.y : in[r][k >> 1].f.x;
            xd[r].f.x = v;
            xd[r].f.y = v;
        }
#pragma unroll
        for (int a = 0; a < H; ++a) {
            // Natural W pair {W[k][2a], W[k][2a+1]} - row-major, 8B aligned
            const u64 w = *reinterpret_cast<const u64*>(cAll + WO + k * OUT + 2 * a);
#pragma unroll
            for (int r = 0; r < 4; ++r)
                out[r][a].u = ffma2(xd[r].u, w, out[r][a].u);
        }
    }

    if (RELU) {
#pragma unroll
        for (int a = 0; a < H; ++a)
#pragma unroll
            for (int r = 0; r < 4; ++r) {
                out[r][a].f.x = fmaxf(out[r][a].f.x, 0.0f);
                out[r][a].f.y = fmaxf(out[r][a].f.y, 0.0f);
            }
    }
}

__global__ void __launch_bounds__(THREADS)
mlp_fused_kernel(const float* __restrict__ x, float* __restrict__ out, int rows)
{
    const int tid = threadIdx.x;

    // --- Row assignment: 4 independent rows per thread, coalesced ---------
    const long base = (long)blockIdx.x * ROWS_PER_BLOCK;
    const int r0 = (int)base + tid;
    const int r1 = r0 + THREADS;
    const int r2 = r0 + 2 * THREADS;
    const int r3 = r0 + 3 * THREADS;
    const bool g0 = r0 < rows, g1 = r1 < rows, g2 = r2 < rows, g3 = r3 < rows;

    const float4* __restrict__ X = (const float4*)x;
    const float4 z4 = make_float4(0.f, 0.f, 0.f, 0.f);
    float4 va[4], vb[4];
    va[0] = g0 ? X[2 * r0] : z4;  vb[0] = g0 ? X[2 * r0 + 1] : z4;
    va[1] = g1 ? X[2 * r1] : z4;  vb[1] = g1 ? X[2 * r1 + 1] : z4;
    va[2] = g2 ? X[2 * r2] : z4;  vb[2] = g2 ? X[2 * r2 + 1] : z4;
    va[3] = g3 ? X[2 * r3] : z4;  vb[3] = g3 ? X[2 * r3 + 1] : z4;

    // Ping-pong banks: [row][pair], pair a = {z_2a, z_2a+1}
    F2 A[4][10], B[4][10];
#pragma unroll
    for (int r = 0; r < 4; ++r) {
        A[r][0].f = make_float2(va[r].x, va[r].y);
        A[r][1].f = make_float2(va[r].z, va[r].w);
        A[r][2].f = make_float2(vb[r].x, vb[r].y);
        A[r][3].f = make_float2(vb[r].z, vb[r].w);
    }

    // --- 9 even layers (ping-pong A <-> B), weights via constant port -----
    layer< 8, 20,    0,   0, true>(A, B);
    layer<20, 18,  160,  20, true>(B, A);
    layer<18, 16,  520,  38, true>(A, B);
    layer<16, 14,  808,  54, true>(B, A);
    layer<14, 12, 1032,  68, true>(A, B);
    layer<12, 10, 1200,  80, true>(B, A);
    layer<10,  8, 1320,  90, true>(A, B);
    layer< 8,  6, 1400,  98, true>(B, A);
    layer< 6,  4, 1448, 104, true>(A, B);

    // --- Last layer (4 -> 1): natural pairs line up ------------------------
    const u64 w01 = *reinterpret_cast<const u64*>(cAll + 1472);     // {W9[0],W9[1]}
    const u64 w23 = *reinterpret_cast<const u64*>(cAll + 1474);     // {W9[2],W9[3]}
    const float b9 = cAll[NWF + 108];
    F2 bz; bz.f = make_float2(b9, 0.0f);
    float z[4];
#pragma unroll
    for (int r = 0; r < 4; ++r) {
        F2 t;
        t.u = ffma2(B[r][0].u, w01, bz.u);
        t.u = ffma2(B[r][1].u, w23, t.u);
        z[r] = t.f.x + t.f.y;
    }

    // --- Sigmoid + store --------------------------------------------------
    if (g0) out[r0] = sigf(z[0]);
    if (g1) out[r1] = sigf(z[1]);
    if (g2) out[r2] = sigf(z[2]);
    if (g3) out[r3] = sigf(z[3]);
}

extern "C" void kernel_launch(void* const* d_in, const int* in_sizes, int n_in,
                              void* d_out, int out_size)
{
    const float* x = (const float*)d_in[0];
    Params p;
    for (int i = 0; i < 10; ++i) {
        p.W[i] = (const float*)d_in[1 + 2 * i];
        p.b[i] = (const float*)d_in[2 + 2 * i];
    }
    const int rows = in_sizes[0] / 8;   // x is [rows, 8] fp32

    // 1) Gather W/b into device staging array (kernel, capturable)
    gather_kernel<<<1, THREADS>>>(p);

    // 2) Device-to-device copy into the constant bank (async memcpy node,
    //    graph-capturable; no allocation; deterministic every replay)
    void* stage_ptr = nullptr;
    cudaGetSymbolAddress(&stage_ptr, g_stage);
    cudaMemcpyToSymbolAsync(cAll, stage_ptr, NALL * sizeof(float), 0,
                            cudaMemcpyDeviceToDevice);

    // 3) Main fused MLP, weights served by the constant port
    const int grid = (rows + ROWS_PER_BLOCK - 1) / ROWS_PER_BLOCK;
    mlp_fused_kernel<<<grid, THREADS>>>(x, (float*)d_out, rows);
}